// round 11
// baseline (speedup 1.0000x reference)
#include <cuda_runtime.h>
#include <cuda_fp16.h>
#include <cstdint>

#define NN 32
#define PP 256
#define FF 256
#define BB 64
#define BC 512
#define OUTC 320
#define LOG2E 1.44269504088896340736f

// ---------------- device scratch ----------------
__device__ __half g_Th[BC * FF];          // [n=512][k=256] fp16, pre-scaled by log2(e)

// ---------------- helpers ----------------
__device__ __forceinline__ uint32_t smem_u32(const void* p) {
    uint32_t a;
    asm("{ .reg .u64 t; cvta.to.shared.u64 t, %1; cvt.u32.u64 %0, t; }"
        : "=r"(a) : "l"(p));
    return a;
}

#define LDSM4(r, addr) \
    asm volatile("ldmatrix.sync.aligned.m8n8.x4.shared.b16 {%0,%1,%2,%3}, [%4];" \
        : "=r"((r)[0]), "=r"((r)[1]), "=r"((r)[2]), "=r"((r)[3]) : "r"(addr))

#define MMA_F16(c, a, b0, b1) \
    asm volatile("mma.sync.aligned.m16n8k16.row.col.f32.f16.f16.f32 " \
        "{%0,%1,%2,%3}, {%4,%5,%6,%7}, {%8,%9}, {%0,%1,%2,%3};" \
        : "+f"((c)[0]), "+f"((c)[1]), "+f"((c)[2]), "+f"((c)[3]) \
        : "r"((a)[0]), "r"((a)[1]), "r"((a)[2]), "r"((a)[3]), "r"(b0), "r"(b1))

__device__ __forceinline__ void cp16(uint32_t dst, const void* src) {
    asm volatile("cp.async.cg.shared.global [%0], [%1], 16;"
                 :: "r"(dst), "l"(src) : "memory");
}
#define CP_COMMIT() asm volatile("cp.async.commit_group;" ::: "memory")
#define CP_WAIT(n)  asm volatile("cp.async.wait_group %0;" :: "n"(n) : "memory")

__device__ __forceinline__ unsigned long long fma2(unsigned long long a,
                                                   unsigned long long b,
                                                   unsigned long long c) {
    unsigned long long d;
    asm("fma.rn.f32x2 %0, %1, %2, %3;" : "=l"(d) : "l"(a), "l"(b), "l"(c));
    return d;
}
__device__ __forceinline__ unsigned long long add2(unsigned long long a,
                                                   unsigned long long b) {
    unsigned long long d;
    asm("add.rn.f32x2 %0, %1, %2;" : "=l"(d) : "l"(a), "l"(b));
    return d;
}
__device__ __forceinline__ float ex2(float s) {
    float r;
    asm("ex2.approx.f32 %0, %1;" : "=f"(r) : "f"(s));
    return r;
}

// =============== prep: T transpose + scale -> fp16 K-major ===============
__global__ __launch_bounds__(256)
void mbd_prep_t(const float* __restrict__ T) {
    __shared__ float tile[32][33];
    const int t = threadIdx.x;
    const int f0 = (blockIdx.x & 7) * 32;
    const int n0 = (blockIdx.x >> 3) * 32;
    const int tx = t & 31;
    const int ty = t >> 5;
    #pragma unroll
    for (int r = 0; r < 4; ++r)
        tile[ty + 8 * r][tx] = T[(size_t)(f0 + ty + 8 * r) * BC + n0 + tx];
    __syncthreads();
    #pragma unroll
    for (int r = 0; r < 4; ++r) {
        int n = n0 + ty + 8 * r;
        int f = f0 + tx;
        g_Th[(size_t)n * FF + f] = __float2half(tile[tx][ty + 8 * r] * LOG2E);
    }
}

// =============== fused: x-split + GEMM (64x128x256) + symmetric pairwise ===============
#define PAD 72                 // half-elements per row in A/B smem tiles
// smem byte offsets
#define AH_OFF  0              // A hi: 64*72*2  = 9216
#define AL_OFF  9216           // A lo: 9216
#define F32_OFF 18432          // fp32 x staging: 64*64*4 = 16384
#define B0_OFF  34816          // B stage 0: 128*72*2 = 18432
#define B1_OFF  53248          // B stage 1: 18432
#define SMEM_FUSED 71680
#define MROW 132               // padded M row (floats)
#define MS_OFF 0               // Ms: 64*132*4 = 33792 (pair phase; GEMM done)
#define OPART_OFF 33792        // [32 grp][4 slot][32 i] *4B = 16384

__global__ __launch_bounds__(256, 3)
void mbd_fused(const float* __restrict__ x, float* __restrict__ out) {
    extern __shared__ char smem[];
    const uint32_t smb = smem_u32(smem);
    float* F32buf = reinterpret_cast<float*>(smem + F32_OFF);
    float* Ms     = reinterpret_cast<float*>(smem + MS_OFF);
    float* o_part = reinterpret_cast<float*>(smem + OPART_OFF);
    const int t = threadIdx.x, w = t >> 5, lane = t & 31;
    const int bx = blockIdx.x;                  // 128 pixel-pairs
    const int by = blockIdx.y;                  // 4 tiles: 16 b AND f-chunk for passthrough
    const int mo = (w >> 2) * 32;               // 0,32
    const int no = (w & 3) * 32;                // 0..96

    float acc[2][4][4];
    #pragma unroll
    for (int i = 0; i < 2; ++i)
        #pragma unroll
        for (int j = 0; j < 4; ++j)
            #pragma unroll
            for (int e = 0; e < 4; ++e) acc[i][j][e] = 0.f;

    // stage raw fp32 A chunk kc into F32buf
    auto stageA = [&](int kc) {
        #pragma unroll
        for (int it = 0; it < 4; ++it) {
            int idx = t + 256 * it;            // 0..1023 (16B chunks)
            int row = idx >> 4, c4 = idx & 15;
            int p = bx * 2 + (row >> 5), n = row & 31;
            cp16(smb + F32_OFF + (uint32_t)(row * 64 + c4 * 4) * 4,
                 x + (size_t)(n * PP + p) * FF + kc * 64 + c4 * 4);
        }
    };
    // stage B chunk kc into buffer s
    auto stageB = [&](int kc, int s) {
        const uint32_t base = smb + (s ? B1_OFF : B0_OFF);
        #pragma unroll
        for (int it = 0; it < 4; ++it) {
            int idx = t + 256 * it;            // 0..1023
            int row = idx >> 3, u = idx & 7;
            cp16(base + (uint32_t)(row * PAD + u * 8) * 2,
                 g_Th + (size_t)(by * 128 + row) * FF + kc * 64 + u * 8);
        }
    };
    // convert F32buf -> A hi/lo halves (+ passthrough when kc==by)
    auto convertA = [&](int kc) {
        const int row = t >> 2, qt = t & 3;
        const int p = bx * 2 + (row >> 5), n = row & 31;
        #pragma unroll
        for (int i = 0; i < 4; ++i) {
            float4 v = *reinterpret_cast<const float4*>(
                &F32buf[row * 64 + qt * 16 + i * 4]);
            if (kc == by)
                *reinterpret_cast<float4*>(
                    out + (size_t)(n * PP + p) * OUTC + kc * 64 + qt * 16 + i * 4) = v;
            __half h0 = __float2half(v.x), h1 = __float2half(v.y);
            __half h2 = __float2half(v.z), h3 = __float2half(v.w);
            __half2 hi0(h0, h1), hi1(h2, h3);
            __half2 lo0(__float2half(v.x - __half2float(h0)),
                        __float2half(v.y - __half2float(h1)));
            __half2 lo1(__float2half(v.z - __half2float(h2)),
                        __float2half(v.w - __half2float(h3)));
            uint32_t off = (uint32_t)(row * PAD + qt * 16 + i * 4) * 2;
            *reinterpret_cast<uint2*>(smem + AH_OFF + off) =
                make_uint2(*reinterpret_cast<uint32_t*>(&hi0),
                           *reinterpret_cast<uint32_t*>(&hi1));
            *reinterpret_cast<uint2*>(smem + AL_OFF + off) =
                make_uint2(*reinterpret_cast<uint32_t*>(&lo0),
                           *reinterpret_cast<uint32_t*>(&lo1));
        }
    };

    // prologue
    stageA(0); stageB(0, 0); CP_COMMIT();
    CP_WAIT(0); __syncthreads();
    convertA(0); __syncthreads();

    for (int kc = 0; kc < 4; ++kc) {
        if (kc < 3) { stageA(kc + 1); stageB(kc + 1, (kc + 1) & 1); CP_COMMIT(); }

        const uint32_t b_base = smb + ((kc & 1) ? B1_OFF : B0_OFF);
        #pragma unroll
        for (int ks = 0; ks < 4; ++ks) {
            uint32_t afh[2][4], afl[2][4];
            #pragma unroll
            for (int mi = 0; mi < 2; ++mi) {
                uint32_t ad = smb + AH_OFF +
                    (uint32_t)(((mo + mi * 16 + (lane & 15)) * PAD) +
                               ks * 16 + (lane >> 4) * 8) * 2;
                LDSM4(afh[mi], ad);
                LDSM4(afl[mi], ad + (AL_OFF - AH_OFF));
            }
            uint32_t bf[8];
            #pragma unroll
            for (int g = 0; g < 2; ++g) {
                uint32_t bd = b_base +
                    (uint32_t)(((no + g * 16 + ((lane >> 4) & 1) * 8 + (lane & 7)) * PAD) +
                               ks * 16 + ((lane >> 3) & 1) * 8) * 2;
                LDSM4(&bf[g * 4], bd);
            }
            #pragma unroll
            for (int mi = 0; mi < 2; ++mi)
                #pragma unroll
                for (int ni = 0; ni < 4; ++ni) {
                    MMA_F16(acc[mi][ni], afh[mi], bf[ni * 2], bf[ni * 2 + 1]);
                    MMA_F16(acc[mi][ni], afl[mi], bf[ni * 2], bf[ni * 2 + 1]);
                }
        }

        if (kc < 3) {
            CP_WAIT(0); __syncthreads();
            convertA(kc + 1); __syncthreads();
        }
    }
    __syncthreads();   // MMA(3) done before Ms overwrites A/F32 regions

    // ---- epilogue: accumulators -> smem M tile [64 rows][MROW] ----
    #pragma unroll
    for (int mi = 0; mi < 2; ++mi)
        #pragma unroll
        for (int ni = 0; ni < 4; ++ni) {
            int col = no + ni * 8 + (lane & 3) * 2;
            #pragma unroll
            for (int h = 0; h < 2; ++h) {
                int row = mo + mi * 16 + (lane >> 2) + h * 8;
                *reinterpret_cast<float2*>(&Ms[row * MROW + col]) =
                    make_float2(acc[mi][ni][h * 2], acc[mi][ni][h * 2 + 1]);
            }
        }
    __syncthreads();

    // ---- symmetric pairwise L1 + exp2 (R8 scheme) ----
    const int p_l = t >> 7;
    const int rem = t & 127;
    const int b_l = rem >> 3;
    const int io  = rem & 7;
    const int grp = p_l * 16 + b_l;           // 0..31
    const unsigned long long NEG1 = 0xBF800000BF800000ULL;
    const unsigned long long AMSK = 0x7FFFFFFF7FFFFFFFULL;

    const int p_g = bx * 2 + p_l;
    const int b_g = by * 16 + b_l;

    unsigned long long mi[4][4];
    #pragma unroll
    for (int ii = 0; ii < 4; ++ii) {
        const ulonglong2* row = reinterpret_cast<const ulonglong2*>(
            &Ms[(p_l * 32 + io * 4 + ii) * MROW + b_l * 8]);
        ulonglong2 r0 = row[0], r1 = row[1];
        mi[ii][0] = r0.x; mi[ii][1] = r0.y;
        mi[ii][2] = r1.x; mi[ii][3] = r1.y;
    }
    float rowacc[4] = {0.f, 0.f, 0.f, 0.f};

    #pragma unroll
    for (int s = 0; s <= 4; ++s) {
        if (s == 4 && io >= 4) break;
        const int bblk = (io + s) & 7;
        float cacc[4] = {0.f, 0.f, 0.f, 0.f};
        #pragma unroll
        for (int jj = 0; jj < 4; ++jj) {
            const ulonglong2* row = reinterpret_cast<const ulonglong2*>(
                &Ms[(p_l * 32 + bblk * 4 + jj) * MROW + b_l * 8]);
            ulonglong2 r0 = row[0], r1 = row[1];
            unsigned long long jv0 = r0.x, jv1 = r0.y, jv2 = r1.x, jv3 = r1.y;
            #pragma unroll
            for (int ii = 0; ii < 4; ++ii) {
                unsigned long long d0 = fma2(jv0, NEG1, mi[ii][0]) & AMSK;
                unsigned long long d1 = fma2(jv1, NEG1, mi[ii][1]) & AMSK;
                unsigned long long d2 = fma2(jv2, NEG1, mi[ii][2]) & AMSK;
                unsigned long long d3 = fma2(jv3, NEG1, mi[ii][3]) & AMSK;
                unsigned long long s2 = add2(add2(d0, d1), add2(d2, d3));
                float sv = -__uint_as_float((uint32_t)s2) -
                            __uint_as_float((uint32_t)(s2 >> 32));
                float e = ex2(sv);
                rowacc[ii] += e;
                if (s) cacc[jj] += e;
            }
        }
        if (s) {
            float* dst = &o_part[(grp * 4 + (s - 1)) * 32 + bblk * 4];
            dst[0] = cacc[0]; dst[1] = cacc[1];
            dst[2] = cacc[2]; dst[3] = cacc[3];
        }
    }
    __syncthreads();

    #pragma unroll
    for (int ii = 0; ii < 4; ++ii) {
        int i = io * 4 + ii;
        float v = rowacc[ii]
                + o_part[(grp * 4 + 0) * 32 + i]
                + o_part[(grp * 4 + 1) * 32 + i]
                + o_part[(grp * 4 + 2) * 32 + i];
        if (io >= 4) v += o_part[(grp * 4 + 3) * 32 + i];
        out[(size_t)(i * PP + p_g) * OUTC + FF + b_g] = v;
    }
}

// =============== launch ===============
extern "C" void kernel_launch(void* const* d_in, const int* in_sizes, int n_in,
                              void* d_out, int out_size) {
    const float* x;
    const float* T;
    if (in_sizes[0] == NN * PP * FF) {
        x = (const float*)d_in[0];
        T = (const float*)d_in[1];
    } else {
        x = (const float*)d_in[1];
        T = (const float*)d_in[0];
    }
    float* out = (float*)d_out;

    cudaFuncSetAttribute(mbd_fused,
                         cudaFuncAttributeMaxDynamicSharedMemorySize, SMEM_FUSED);

    mbd_prep_t<<<128, 256>>>(T);
    mbd_fused<<<dim3(128, 4), 256, SMEM_FUSED>>>(x, out);
}